// round 11
// baseline (speedup 1.0000x reference)
#include <cuda_runtime.h>
#include <cstdint>

#define V      81616
#define BATCH  4096
#define DIM    32
#define SPLITS 18
#define SPAN   4544            // 142*32; last split span 4368
#define KC     32
#define NW     192             // decoder column span per CTA

// Scratch (static device globals — allocation-free)
__device__ float g_part[SPLITS * BATCH * DIM];   // split-K partials
__device__ float g_hs[BATCH * DIM];              // sigmoid(hidden)
__device__ float g_wc[V * DIM];                  // w pre-rounded to tf32 (rna)

// ---------- helpers ----------
__device__ __forceinline__ void cp16(void* dst_smem, const void* src) {
    unsigned d = (unsigned)__cvta_generic_to_shared(dst_smem);
    asm volatile("cp.async.cg.shared.global [%0], [%1], 16;" :: "r"(d), "l"(src));
}
__device__ __forceinline__ void cp_commit() {
    asm volatile("cp.async.commit_group;");
}
template <int N>
__device__ __forceinline__ void cp_wait() {
    asm volatile("cp.async.wait_group %0;" :: "n"(N));
}
__device__ __forceinline__ uint32_t tf32(float f) {
    uint32_t u;
    asm("cvt.rna.tf32.f32 %0, %1;" : "=r"(u) : "f"(f));
    return u;
}
__device__ __forceinline__ void mma8(float& d0, float& d1, float& d2, float& d3,
                                     uint32_t a0, uint32_t a1, uint32_t a2, uint32_t a3,
                                     uint32_t b0, uint32_t b1) {
    asm("mma.sync.aligned.m16n8k8.row.col.f32.tf32.tf32.f32 "
        "{%0,%1,%2,%3}, {%4,%5,%6,%7}, {%8,%9}, {%0,%1,%2,%3};"
        : "+f"(d0), "+f"(d1), "+f"(d2), "+f"(d3)
        : "r"(a0), "r"(a1), "r"(a2), "r"(a3), "r"(b0), "r"(b1));
}
__device__ __forceinline__ float sig_tanh(float z) {
    float t;
    asm("tanh.approx.f32 %0, %1;" : "=f"(t) : "f"(0.5f * z));
    return fmaf(0.5f, t, 0.5f);
}
__device__ __forceinline__ float sig_exact(float z) {
    return __fdividef(1.0f, 1.0f + __expf(-z));
}

// ---------- kernel 0: pre-round w to tf32 (rna) ----------
__global__ void k_wconv(const float* __restrict__ w) {
    int i = blockIdx.x * 1024 + threadIdx.x * 4;
    if (i + 3 < V * DIM) {
        float4 v = *(const float4*)(w + i);
        uint4 o;
        o.x = tf32(v.x); o.y = tf32(v.y); o.z = tf32(v.z); o.w = tf32(v.w);
        *(uint4*)(g_wc + i) = o;
    } else if (i < V * DIM) {
        for (int t = i; t < V * DIM; t++)
            *(uint32_t*)(g_wc + t) = tf32(w[t]);
    }
}

// ---------- kernel 1: encoder (unchanged from R9) ----------
__global__ __launch_bounds__(256, 4) void k_encoder(const float* __restrict__ x) {
    __shared__ __align__(16) float xs[2][128][36];
    __shared__ __align__(16) float ws[2][32][40];

    int tid  = threadIdx.x;
    int warp = tid >> 5, lane = tid & 31;
    int l4 = lane >> 2, lm4 = lane & 3;
    int wr0 = warp * 16;
    int row0  = blockIdx.x * 128;
    int split = blockIdx.y;
    int k0    = split * SPAN;
    int kspan = min(SPAN, V - k0);
    int nstg  = (kspan + KC - 1) / KC;

    const size_t XMAX = (size_t)BATCH * V - 4;

    float acc[4][4];
#pragma unroll
    for (int j = 0; j < 4; j++)
#pragma unroll
        for (int c = 0; c < 4; c++) acc[j][c] = 0.0f;

    int wkl = tid >> 3, wc = tid & 7;

    auto stage = [&](int s, int slot) {
        int kb = k0 + s * KC;
#pragma unroll
        for (int i = 0; i < 4; i++) {
            int idx = tid + 256 * i;
            int r = idx >> 3, c = idx & 7;
            size_t off = (size_t)(row0 + r) * V + kb + (c << 2);
            if (off > XMAX) off = XMAX;
            cp16(&xs[slot][r][c << 2], x + off);
        }
        if (kb + wkl < V) {
            cp16(&ws[slot][wkl][wc << 2], g_wc + (size_t)(kb + wkl) * DIM + (wc << 2));
        } else {
            *(float4*)&ws[slot][wkl][wc << 2] = make_float4(0.f, 0.f, 0.f, 0.f);
        }
    };

    stage(0, 0);
    cp_commit();

#pragma unroll 1
    for (int s = 0; s < nstg; s++) {
        int slot = s & 1;
        if (s + 1 < nstg) {
            stage(s + 1, slot ^ 1);
            cp_commit();
            cp_wait<1>();
        } else {
            cp_commit();
            cp_wait<0>();
        }
        __syncthreads();

        const uint32_t* xsb = (const uint32_t*)&xs[slot][wr0 + l4][lm4];
        const uint32_t* wsb = (const uint32_t*)&ws[slot][lm4][l4];
#pragma unroll
        for (int kk = 0; kk < 4; kk++) {
            uint32_t a0 = xsb[kk * 8];
            uint32_t a1 = xsb[288 + kk * 8];
            uint32_t a2 = xsb[kk * 8 + 4];
            uint32_t a3 = xsb[288 + kk * 8 + 4];
#pragma unroll
            for (int j = 0; j < 4; j++) {
                uint32_t b0 = wsb[kk * 320 + j * 8];
                uint32_t b1 = wsb[kk * 320 + 160 + j * 8];
                mma8(acc[j][0], acc[j][1], acc[j][2], acc[j][3],
                     a0, a1, a2, a3, b0, b1);
            }
        }
        __syncthreads();
    }

    float* p = g_part + (size_t)split * (BATCH * DIM)
             + (size_t)(row0 + wr0 + l4) * DIM + lm4 * 2;
#pragma unroll
    for (int j = 0; j < 4; j++) {
        *(float2*)(p + j * 8)            = make_float2(acc[j][0], acc[j][1]);
        *(float2*)(p + 8 * DIM + j * 8)  = make_float2(acc[j][2], acc[j][3]);
    }
}

// ---------- kernel 2: reduce partials + bias + sigmoid (exact) ----------
__global__ void k_hidden(const float* __restrict__ b) {
    int i = blockIdx.x * 256 + threadIdx.x;
    float s = 0.0f;
#pragma unroll
    for (int c = 0; c < SPLITS; c++) s += g_part[(size_t)c * (BATCH * DIM) + i];
    s += b[i & 31];
    g_hs[i] = sig_exact(s);
}

// ---------- kernel 3: decoder, M=256/CTA, batched coalesced stores ----------
// dynamic smem partitions (floats), all rows 16B-aligned (pads are mult. of 4):
//   wv  [NW][36]      = 6912
//   hs  [128][36]     = 4608
//   sb  [8][16][36]   = 4608   (per-warp store-batch buffer)
#define SM_WV   0
#define SM_HS   (NW * 36)
#define SM_SB   (SM_HS + 128 * 36)
#define SM_FLTS (SM_SB + 8 * 16 * 36)

__global__ __launch_bounds__(256) void k_decoder(float* __restrict__ out) {
    extern __shared__ __align__(16) float sm[];
    float* wv_s = sm + SM_WV;
    float* hs_s = sm + SM_HS;

    int tid  = threadIdx.x;
    int warp = tid >> 5, lane = tid & 31;
    int l4 = lane >> 2, lm4 = lane & 3;
    int wr0 = warp * 16;
    int m0 = blockIdx.y * 256;
    int n0 = blockIdx.x * NW;
    float* sb = sm + SM_SB + warp * (16 * 36);

    // stage w tile once (NW rows)
#pragma unroll
    for (int i = 0; i < 6; i++) {
        int idx = tid + 256 * i;
        int vrow = idx >> 3, c = idx & 7;
        int vs = n0 + vrow;
        if (vs > V - 1) vs = V - 1;
        cp16(&wv_s[vrow * 36 + (c << 2)], g_wc + (size_t)vs * DIM + (c << 2));
    }
    // stage hs half 0
#pragma unroll
    for (int i = 0; i < 4; i++) {
        int idx = tid + 256 * i;
        int r = idx >> 3, c = idx & 7;
        cp16(&hs_s[r * 36 + (c << 2)], g_hs + (size_t)(m0 + r) * DIM + (c << 2));
    }
    cp_commit();
    cp_wait<0>();
    __syncthreads();

    int jmax  = min(NW / 8, (V - n0) >> 3);   // V multiple of 8
    int nfull = jmax & ~3;
    const uint32_t* wb = (const uint32_t*)&wv_s[l4 * 36 + lm4];

#pragma unroll 1
    for (int h = 0; h < 2; h++) {
        // A frags for this half
        uint32_t ua[4][4];
        const float* hb = &hs_s[(wr0 + l4) * 36 + lm4];
#pragma unroll
        for (int kk = 0; kk < 4; kk++) {
            ua[kk][0] = tf32(hb[kk * 8]);
            ua[kk][1] = tf32(hb[288 + kk * 8]);
            ua[kk][2] = tf32(hb[kk * 8 + 4]);
            ua[kk][3] = tf32(hb[288 + kk * 8 + 4]);
        }

        int rbase = m0 + h * 128 + wr0;

        // full batches of 4 j (32 cols) -> smem -> coalesced STG.128
#pragma unroll 1
        for (int jb = 0; jb < nfull; jb += 4) {
#pragma unroll
            for (int jj = 0; jj < 4; jj++) {
                int j = jb + jj;
                float d0 = 0.f, d1 = 0.f, d2 = 0.f, d3 = 0.f;
#pragma unroll
                for (int kk = 0; kk < 4; kk++) {
                    uint32_t b0 = wb[j * 288 + kk * 8];
                    uint32_t b1 = wb[j * 288 + kk * 8 + 4];
                    mma8(d0, d1, d2, d3,
                         ua[kk][0], ua[kk][1], ua[kk][2], ua[kk][3], b0, b1);
                }
                int c = jj * 8 + lm4 * 2;
                *(float2*)&sb[l4 * 36 + c]       = make_float2(sig_tanh(d0), sig_tanh(d1));
                *(float2*)&sb[(l4 + 8) * 36 + c] = make_float2(sig_tanh(d2), sig_tanh(d3));
            }
            __syncwarp();
            // readback + store: 4 row-groups of 4 rows x 128 B (each 8-lane
            // phase reads one contiguous 128B row segment: conflict-free)
            int rr = lane >> 3, cc = (lane & 7) << 2;
#pragma unroll
            for (int g = 0; g < 4; g++) {
                float4 v = *(const float4*)&sb[(g * 4 + rr) * 36 + cc];
                __stcs((float4*)(out + (size_t)(rbase + g * 4 + rr) * V
                                 + n0 + jb * 8 + cc), v);
            }
            __syncwarp();
        }

        // tail j's (last col-block): direct stores
        for (int j = nfull; j < jmax; j++) {
            float d0 = 0.f, d1 = 0.f, d2 = 0.f, d3 = 0.f;
#pragma unroll
            for (int kk = 0; kk < 4; kk++) {
                uint32_t b0 = wb[j * 288 + kk * 8];
                uint32_t b1 = wb[j * 288 + kk * 8 + 4];
                mma8(d0, d1, d2, d3,
                     ua[kk][0], ua[kk][1], ua[kk][2], ua[kk][3], b0, b1);
            }
            float* o0 = out + (size_t)(rbase + l4) * V + n0 + j * 8 + lm4 * 2;
            *(float2*)o0 = make_float2(sig_tanh(d0), sig_tanh(d1));
            *(float2*)(o0 + (size_t)8 * V) = make_float2(sig_tanh(d2), sig_tanh(d3));
        }

        // restage hs for half 1
        if (h == 0) {
            __syncthreads();
#pragma unroll
            for (int i = 0; i < 4; i++) {
                int idx = tid + 256 * i;
                int r = idx >> 3, c = idx & 7;
                cp16(&hs_s[r * 36 + (c << 2)],
                     g_hs + (size_t)(m0 + 128 + r) * DIM + (c << 2));
            }
            cp_commit();
            cp_wait<0>();
            __syncthreads();
        }
    }
}

extern "C" void kernel_launch(void* const* d_in, const int* in_sizes, int n_in,
                              void* d_out, int out_size) {
    const float* x = (const float*)d_in[0];
    const float* w = (const float*)d_in[1];
    const float* b = (const float*)d_in[2];
    float* out = (float*)d_out;

    cudaFuncSetAttribute(k_decoder, cudaFuncAttributeMaxDynamicSharedMemorySize,
                         SM_FLTS * 4);

    k_wconv<<<(V * DIM + 1023) / 1024, 256>>>(w);
    k_encoder<<<dim3(BATCH / 128, SPLITS), 256>>>(x);
    k_hidden<<<(BATCH * DIM) / 256, 256>>>(b);
    k_decoder<<<dim3((V + NW - 1) / NW, BATCH / 256), 256, SM_FLTS * 4>>>(out);
}

// round 12
// speedup vs baseline: 1.0839x; 1.0839x over previous
#include <cuda_runtime.h>
#include <cstdint>

#define V      81616
#define VT     81664           // transposed-w padded k extent (mult of 64)
#define BATCH  4096
#define DIM    32
#define SPLITS 18
#define SPAN   4544            // 142*32; last split span 4368 -> 137 stages
#define KC     32
#define NW     192             // decoder column span per CTA

// Scratch (static device globals — allocation-free)
__device__ float g_part[SPLITS * BATCH * DIM];   // split-K partials
__device__ float g_hs[BATCH * DIM];              // sigmoid(hidden)
__device__ float g_wc[V * DIM];                  // w pre-rounded tf32, natural [v][d]
__device__ float g_wcT[DIM * VT];                // w pre-rounded tf32, transposed [d][k], zero tail

// ---------- helpers ----------
__device__ __forceinline__ void cp16(void* dst_smem, const void* src) {
    unsigned d = (unsigned)__cvta_generic_to_shared(dst_smem);
    asm volatile("cp.async.cg.shared.global [%0], [%1], 16;" :: "r"(d), "l"(src));
}
__device__ __forceinline__ void cp_commit() {
    asm volatile("cp.async.commit_group;");
}
template <int N>
__device__ __forceinline__ void cp_wait() {
    asm volatile("cp.async.wait_group %0;" :: "n"(N));
}
__device__ __forceinline__ uint32_t tf32(float f) {
    uint32_t u;
    asm("cvt.rna.tf32.f32 %0, %1;" : "=r"(u) : "f"(f));
    return u;
}
__device__ __forceinline__ void mma8(float& d0, float& d1, float& d2, float& d3,
                                     uint32_t a0, uint32_t a1, uint32_t a2, uint32_t a3,
                                     uint32_t b0, uint32_t b1) {
    asm("mma.sync.aligned.m16n8k8.row.col.f32.tf32.tf32.f32 "
        "{%0,%1,%2,%3}, {%4,%5,%6,%7}, {%8,%9}, {%0,%1,%2,%3};"
        : "+f"(d0), "+f"(d1), "+f"(d2), "+f"(d3)
        : "r"(a0), "r"(a1), "r"(a2), "r"(a3), "r"(b0), "r"(b1));
}
__device__ __forceinline__ float sig_tanh(float z) {
    float t;
    asm("tanh.approx.f32 %0, %1;" : "=f"(t) : "f"(0.5f * z));
    return fmaf(0.5f, t, 0.5f);
}
__device__ __forceinline__ float sig_exact(float z) {
    return __fdividef(1.0f, 1.0f + __expf(-z));
}
__device__ __forceinline__ uint32_t fb(float f) { return __float_as_uint(f); }

// ---------- kernel 0a: pre-round w to tf32 (natural layout, for decoder) ----------
__global__ void k_wconv(const float* __restrict__ w) {
    int i = blockIdx.x * 1024 + threadIdx.x * 4;
    if (i + 3 < V * DIM) {
        float4 v = *(const float4*)(w + i);
        uint4 o;
        o.x = tf32(v.x); o.y = tf32(v.y); o.z = tf32(v.z); o.w = tf32(v.w);
        *(uint4*)(g_wc + i) = o;
    } else if (i < V * DIM) {
        for (int t = i; t < V * DIM; t++)
            *(uint32_t*)(g_wc + t) = tf32(w[t]);
    }
}

// ---------- kernel 0b: transpose + round w -> g_wcT[32][VT], zero tail ----------
__global__ void k_wconvT(const float* __restrict__ w) {
    __shared__ float s[64][33];
    int k0 = blockIdx.x * 64;
    int tid = threadIdx.x; // 256 threads
#pragma unroll
    for (int i = 0; i < 8; i++) {
        int idx = tid + i * 256;
        int r = idx >> 5, d = idx & 31;
        int k = k0 + r;
        s[r][d] = (k < V) ? __uint_as_float(tf32(w[(size_t)k * DIM + d])) : 0.0f;
    }
    __syncthreads();
#pragma unroll
    for (int i = 0; i < 8; i++) {
        int idx = tid + i * 256;
        int d = idx >> 6, c = idx & 63;
        g_wcT[(size_t)d * VT + k0 + c] = s[c][d];
    }
}

// ---------- kernel 1: encoder, k-permuted frags, all LDS.128 ----------
// xs/ws: 32-float rows, XOR-16 swizzle on odd rows -> conflict-free LDS.128.
// MMA k-block kk = physical cols {kk, kk+4, ..., kk+28} (same perm on A and B).
__global__ __launch_bounds__(256, 4) void k_encoder(const float* __restrict__ x) {
    __shared__ __align__(16) float xs[2][128 * 32];  // 32 KB
    __shared__ __align__(16) float ws[2][32 * 32];   //  8 KB

    int tid  = threadIdx.x;
    int warp = tid >> 5, lane = tid & 31;
    int l4 = lane >> 2, lm4 = lane & 3;
    int wr0 = warp * 16;
    int row0  = blockIdx.x * 128;
    int split = blockIdx.y;
    int k0    = split * SPAN;
    int kspan = min(SPAN, V - k0);
    int nstg  = (kspan + KC - 1) / KC;

    const size_t XMAX = (size_t)BATCH * V - 4;

    float acc[4][4];
#pragma unroll
    for (int j = 0; j < 4; j++)
#pragma unroll
        for (int c = 0; c < 4; c++) acc[j][c] = 0.0f;

    int wd = tid >> 3, wcc = tid & 7;   // w staging: dim-row, 16B chunk

    auto stage = [&](int s, int slot) {
        int kb = k0 + s * KC;
#pragma unroll
        for (int i = 0; i < 4; i++) {
            int idx = tid + 256 * i;
            int r = idx >> 3, cc = idx & 7;
            size_t off = (size_t)(row0 + r) * V + kb + (cc << 2);
            if (off > XMAX) off = XMAX;   // finite garbage; matching wT rows are zero
            cp16(&xs[slot][r * 32 + (((cc << 2)) ^ ((r & 1) << 4))], x + off);
        }
        cp16(&ws[slot][wd * 32 + (((wcc << 2)) ^ ((wd & 1) << 4))],
             g_wcT + (size_t)wd * VT + kb + (wcc << 2));
    };

    stage(0, 0);
    cp_commit();

    int pa = (l4 & 1) << 4;
    int caLo = ((lm4 << 2) ^ pa) >> 2;   // float4 index of low half
    int caHi = caLo ^ 4 >> 2;            // (^16 floats) = ^4 float4s
    caHi = caLo ^ 4;

#pragma unroll 1
    for (int s = 0; s < nstg; s++) {
        int slot = s & 1;
        if (s + 1 < nstg) {
            stage(s + 1, slot ^ 1);
            cp_commit();
            cp_wait<1>();
        } else {
            cp_commit();
            cp_wait<0>();
        }
        __syncthreads();

        const float4* xrL = (const float4*)&xs[slot][(wr0 + l4) * 32];
        const float4* xrH = (const float4*)&xs[slot][(wr0 + l4 + 8) * 32];
        float4 aL0 = xrL[caLo];   // a0[kk]
        float4 aL1 = xrL[caHi];   // a2[kk]
        float4 aH0 = xrH[caLo];   // a1[kk]
        float4 aH1 = xrH[caHi];   // a3[kk]

#pragma unroll
        for (int jp = 0; jp < 2; jp++) {
            const float4* br0 = (const float4*)&ws[slot][((jp * 2) * 8 + l4) * 32];
            const float4* br1 = (const float4*)&ws[slot][((jp * 2 + 1) * 8 + l4) * 32];
            float4 b00 = br0[caLo], b01 = br0[caHi];
            float4 b10 = br1[caLo], b11 = br1[caHi];
#pragma unroll
            for (int kk = 0; kk < 4; kk++) {
                uint32_t a0 = fb(((const float*)&aL0)[kk]);
                uint32_t a1 = fb(((const float*)&aH0)[kk]);
                uint32_t a2 = fb(((const float*)&aL1)[kk]);
                uint32_t a3 = fb(((const float*)&aH1)[kk]);
                mma8(acc[jp * 2][0], acc[jp * 2][1], acc[jp * 2][2], acc[jp * 2][3],
                     a0, a1, a2, a3,
                     fb(((const float*)&b00)[kk]), fb(((const float*)&b01)[kk]));
                mma8(acc[jp * 2 + 1][0], acc[jp * 2 + 1][1], acc[jp * 2 + 1][2], acc[jp * 2 + 1][3],
                     a0, a1, a2, a3,
                     fb(((const float*)&b10)[kk]), fb(((const float*)&b11)[kk]));
            }
        }
        __syncthreads();
    }

    float* p = g_part + (size_t)split * (BATCH * DIM)
             + (size_t)(row0 + wr0 + l4) * DIM + lm4 * 2;
#pragma unroll
    for (int j = 0; j < 4; j++) {
        *(float2*)(p + j * 8)            = make_float2(acc[j][0], acc[j][1]);
        *(float2*)(p + 8 * DIM + j * 8)  = make_float2(acc[j][2], acc[j][3]);
    }
}

// ---------- kernel 2: reduce partials + bias + sigmoid (exact) ----------
__global__ void k_hidden(const float* __restrict__ b) {
    int i = blockIdx.x * 256 + threadIdx.x;
    float s = 0.0f;
#pragma unroll
    for (int c = 0; c < SPLITS; c++) s += g_part[(size_t)c * (BATCH * DIM) + i];
    s += b[i & 31];
    g_hs[i] = sig_exact(s);
}

// ---------- kernel 3: decoder (R9 structure) + vectorized k-permuted B frags ----------
__global__ __launch_bounds__(256, 3) void k_decoder(float* __restrict__ out) {
    __shared__ __align__(16) float hs_s[128 * 32];   // 16 KB, natural
    __shared__ __align__(16) float wv_s[NW * 32];    // 24 KB, swizzled

    int tid  = threadIdx.x;
    int warp = tid >> 5, lane = tid & 31;
    int l4 = lane >> 2, lm4 = lane & 3;
    int wr0 = warp * 16;
    int m0 = blockIdx.y * 128;
    int n0 = blockIdx.x * NW;

#pragma unroll
    for (int i = 0; i < 4; i++) {
        int idx = tid + 256 * i;
        int r = idx >> 3, cc = idx & 7;
        cp16(&hs_s[r * 32 + (cc << 2)], g_hs + (size_t)(m0 + r) * DIM + (cc << 2));
    }
#pragma unroll
    for (int i = 0; i < 6; i++) {
        int idx = tid + 256 * i;
        int vrow = idx >> 3, cc = idx & 7;
        int vs = n0 + vrow;
        if (vs > V - 1) vs = V - 1;
        cp16(&wv_s[vrow * 32 + (((cc << 2)) ^ ((vrow & 1) << 4))],
             g_wc + (size_t)vs * DIM + (cc << 2));
    }
    cp_commit();
    cp_wait<0>();
    __syncthreads();

    // A frags, permuted k: a-element for block kk = phys col lm4*4+kk (lo), +16 (hi)
    uint32_t ua[4][4];
    const float* hb = &hs_s[(wr0 + l4) * 32];
    const float* hb8 = hb + 8 * 32;
#pragma unroll
    for (int kk = 0; kk < 4; kk++) {
        ua[kk][0] = tf32(hb[lm4 * 4 + kk]);
        ua[kk][1] = tf32(hb8[lm4 * 4 + kk]);
        ua[kk][2] = tf32(hb[16 + lm4 * 4 + kk]);
        ua[kk][3] = tf32(hb8[16 + lm4 * 4 + kk]);
    }

    int jmax = min(NW / 8, (V - n0) >> 3);   // V multiple of 8
    int pa = (l4 & 1) << 4;
    int cbLo = ((lm4 << 2) ^ pa) >> 2;
    int cbHi = cbLo ^ 4;
    float* o0 = out + (size_t)(m0 + wr0 + l4) * V + n0 + lm4 * 2;
    float* o1 = o0 + (size_t)8 * V;

#pragma unroll 2
    for (int j = 0; j < jmax; j++) {
        const float4* br = (const float4*)&wv_s[(j * 8 + l4) * 32];
        float4 b0v = br[cbLo];
        float4 b1v = br[cbHi];
        float d0 = 0.f, d1 = 0.f, d2 = 0.f, d3 = 0.f;
#pragma unroll
        for (int kk = 0; kk < 4; kk++) {
            mma8(d0, d1, d2, d3,
                 ua[kk][0], ua[kk][1], ua[kk][2], ua[kk][3],
                 fb(((const float*)&b0v)[kk]), fb(((const float*)&b1v)[kk]));
        }
        *(float2*)(o0 + j * 8) = make_float2(sig_tanh(d0), sig_tanh(d1));
        *(float2*)(o1 + j * 8) = make_float2(sig_tanh(d2), sig_tanh(d3));
    }
}

extern "C" void kernel_launch(void* const* d_in, const int* in_sizes, int n_in,
                              void* d_out, int out_size) {
    const float* x = (const float*)d_in[0];
    const float* w = (const float*)d_in[1];
    const float* b = (const float*)d_in[2];
    float* out = (float*)d_out;

    k_wconv<<<(V * DIM + 1023) / 1024, 256>>>(w);
    k_wconvT<<<VT / 64, 256>>>(w);
    k_encoder<<<dim3(BATCH / 128, SPLITS), 256>>>(x);
    k_hidden<<<(BATCH * DIM) / 256, 256>>>(b);
    k_decoder<<<dim3((V + NW - 1) / NW, BATCH / 128), 256>>>(out);
}